// round 6
// baseline (speedup 1.0000x reference)
#include <cuda_runtime.h>
#include <cuda_bf16.h>
#include <math.h>

#define Nn 100000
#define Ee 1600000
#define Gg 64

// ---------------- packed f32x2 helpers ----------------
#define PACK2(out, a, b) \
    asm("mov.b64 %0, {%1, %2};" : "=l"(out) : "f"(a), "f"(b))
#define FMA2(acc, a, b) \
    asm("fma.rn.f32x2 %0, %1, %2, %0;" : "+l"(acc) : "l"(a), "l"(b))

// ---------------- device scratch (static, no runtime allocation) ----------------
__device__ int   g_cnt[Nn];
__device__ int   g_rowptr[Nn + 1];
__device__ int   g_cursor[Nn];
__device__ int   g_cols[Ee];
__device__ float g_dis[Nn];
__device__ float g_bufA[Nn * 64];
__device__ float g_bufB[Nn * 64];
__device__ float g_stats[3 * 128];      // per layer: [0..H) sum, [H..2H) sumsq
__device__ int   g_bsum[256];           // scan partials
__device__ float g_pool[Gg * 33];       // per graph: sum[16], max[16], count

// ---------------- small utility kernels ----------------
__global__ void k_zero() {
    int i = blockIdx.x * 256 + threadIdx.x;
    if (i < Nn) g_cnt[i] = 0;
    if (i < 3 * 128) g_stats[i] = 0.f;
}
__global__ void k_hist(const int* __restrict__ dst) {
    int e = blockIdx.x * 256 + threadIdx.x;
    if (e < Ee) atomicAdd(&g_cnt[dst[e]], 1);
}

#define SCAN_NB 196   // 196 * 512 = 100352 >= Nn

// scan1: per-block sums of cnt, plus dis = rsqrt(deg) (fused)
__global__ void k_scan1() {
    __shared__ int sh[512];
    int t = threadIdx.x, idx = blockIdx.x * 512 + t;
    int v = (idx < Nn) ? g_cnt[idx] : 0;
    if (idx < Nn) g_dis[idx] = rsqrtf((float)(v + 1));
    sh[t] = v;
    __syncthreads();
    for (int off = 256; off > 0; off >>= 1) {
        if (t < off) sh[t] += sh[t + off];
        __syncthreads();
    }
    if (t == 0) g_bsum[blockIdx.x] = sh[0];
}

// scan3: each block re-scans the 196 block sums in smem (replaces scan2),
// then does its local exclusive scan -> rowptr/cursor.
__global__ void k_scan3() {
    __shared__ int sb[256];
    __shared__ int sh[512];
    int t = threadIdx.x, idx = blockIdx.x * 512 + t;
    if (t < 256) sb[t] = (t < SCAN_NB) ? g_bsum[t] : 0;
    __syncthreads();
    for (int off = 1; off < 256; off <<= 1) {
        int add = 0;
        if (t < 256 && t >= off) add = sb[t - off];
        __syncthreads();
        if (t < 256) sb[t] += add;
        __syncthreads();
    }
    int blockPrefix = (blockIdx.x == 0) ? 0 : sb[blockIdx.x - 1];
    int v = (idx < Nn) ? g_cnt[idx] : 0;
    sh[t] = v;
    __syncthreads();
    for (int off = 1; off < 512; off <<= 1) {
        int add = (t >= off) ? sh[t - off] : 0;
        __syncthreads();
        sh[t] += add;
        __syncthreads();
    }
    if (idx < Nn) {
        int ex = blockPrefix + sh[t] - v;
        g_rowptr[idx] = ex;
        g_cursor[idx] = ex;
    }
    if (idx == 0) g_rowptr[Nn] = Ee;
}
__global__ void k_fill(const int* __restrict__ src, const int* __restrict__ dst) {
    int e = blockIdx.x * 256 + threadIdx.x;
    if (e < Ee) {
        int d = dst[e];
        int p = atomicAdd(&g_cursor[d], 1);
        g_cols[p] = src[e];
    }
}

// ---------------- GEMM (transposed-x register tile, packed f32x2 FMA) ----------------
// out[i,c] = dis[i] * sum_k f(h[i,k]) * W[k,c]
// f = identity (NORM=false) or BN-normalize + leaky relu (NORM=true).
// block = 256 threads, tile = 128 nodes. Thread owns 2 consecutive nodes
// ((tid&63)*2..+1) and C=H/4 channels (group tid>>6). x staged TRANSPOSED
// in smem with stride 130 (conflict-free stores AND loads); W chunk is
// warp-uniform 16B broadcasts.
template <int K, int H, bool NORM>
__global__ void __launch_bounds__(256, 3) k_gemm(const float* __restrict__ h,
                                                 const float* __restrict__ W,
                                                 const float* __restrict__ stats,
                                                 const float* __restrict__ gamma,
                                                 const float* __restrict__ beta,
                                                 float* __restrict__ out) {
    constexpr int C = H / 4;              // channels per thread
    __shared__ float Wsm[16 * H];         // current k-chunk of W
    __shared__ float xt[16][130];         // transposed x chunk (padded stride)
    __shared__ float nsc[K], nsh[K];
    const int tid = threadIdx.x;
    const int base = blockIdx.x * 128;
    const int n0 = (tid & 63) * 2;        // first of 2 owned nodes (local)
    const int cg = tid >> 6;              // channel group 0..3
    const int cbase = cg * C;

    if (NORM) {
        for (int c = tid; c < K; c += 256) {
            float m = stats[c] * (1.0f / Nn);
            float var = stats[K + c] * (1.0f / Nn) - m * m;
            float rstd = rsqrtf(var + 1e-5f);
            float sc = rstd * gamma[c];
            nsc[c] = sc;
            nsh[c] = beta[c] - m * sc;
        }
        __syncthreads();
    }

    unsigned long long acc2[2][C / 2];
#pragma unroll
    for (int t = 0; t < 2; t++)
#pragma unroll
        for (int j = 0; j < C / 2; j++) acc2[t][j] = 0ull;

    for (int kc = 0; kc < K; kc += 16) {
        // stage W chunk [16][H]
        {
            const float4* Wg = reinterpret_cast<const float4*>(W + kc * H);
            float4* Ws = reinterpret_cast<float4*>(Wsm);
#pragma unroll
            for (int i = tid; i < 16 * H / 4; i += 256) Ws[i] = Wg[i];
        }
        // stage x chunk transposed: 512 float4 slots over 256 threads (2 each)
#pragma unroll
        for (int q = 0; q < 2; q++) {
            int f = tid + 256 * q;            // 0..511
            int row = f >> 2, c4 = f & 3;
            int grow = base + row;
            float4 v = make_float4(0.f, 0.f, 0.f, 0.f);
            if (grow < Nn)
                v = *reinterpret_cast<const float4*>(h + (size_t)grow * K + kc + c4 * 4);
            if (NORM) {
                int cb = kc + c4 * 4;
                v.x = v.x * nsc[cb + 0] + nsh[cb + 0]; v.x = v.x > 0.f ? v.x : 0.1f * v.x;
                v.y = v.y * nsc[cb + 1] + nsh[cb + 1]; v.y = v.y > 0.f ? v.y : 0.1f * v.y;
                v.z = v.z * nsc[cb + 2] + nsh[cb + 2]; v.z = v.z > 0.f ? v.z : 0.1f * v.z;
                v.w = v.w * nsc[cb + 3] + nsh[cb + 3]; v.w = v.w > 0.f ? v.w : 0.1f * v.w;
            }
            xt[c4 * 4 + 0][row] = v.x;
            xt[c4 * 4 + 1][row] = v.y;
            xt[c4 * 4 + 2][row] = v.z;
            xt[c4 * 4 + 3][row] = v.w;
        }
        __syncthreads();
#pragma unroll
        for (int kk = 0; kk < 16; kk++) {
            float2 xv = *reinterpret_cast<const float2*>(&xt[kk][n0]);
            unsigned long long x0, x1;
            PACK2(x0, xv.x, xv.x);
            PACK2(x1, xv.y, xv.y);
            const ulonglong2* w2 =
                reinterpret_cast<const ulonglong2*>(&Wsm[kk * H + cbase]);
#pragma unroll
            for (int j = 0; j < C / 4; j++) {
                ulonglong2 w = w2[j];
                FMA2(acc2[0][2 * j + 0], x0, w.x);
                FMA2(acc2[0][2 * j + 1], x0, w.y);
                FMA2(acc2[1][2 * j + 0], x1, w.x);
                FMA2(acc2[1][2 * j + 1], x1, w.y);
            }
        }
        __syncthreads();
    }

    // epilogue: scale by dis[node], store C channels for each of 2 nodes
#pragma unroll
    for (int t = 0; t < 2; t++) {
        int node = base + n0 + t;
        if (node < Nn) {
            float dn = g_dis[node];
            const float* a = reinterpret_cast<const float*>(acc2[t]);
            float* o = out + (size_t)node * H + cbase;
#pragma unroll
            for (int j = 0; j < C / 4; j++) {
                float4 r;
                r.x = a[4 * j + 0] * dn;
                r.y = a[4 * j + 1] * dn;
                r.z = a[4 * j + 2] * dn;
                r.w = a[4 * j + 3] * dn;
                *reinterpret_cast<float4*>(o + 4 * j) = r;
            }
        }
    }
}

// ---------------- gather (H=64): float2 lanes, one warp per node ----------------
__global__ void __launch_bounds__(256) k_gather64(const float* __restrict__ hws,
                                                  const float* __restrict__ b,
                                                  float* __restrict__ pre,
                                                  float* __restrict__ stats) {
    const int lane = threadIdx.x & 31;
    const int c0 = 2 * lane;
    const int warp = (blockIdx.x * blockDim.x + threadIdx.x) >> 5;
    const int nwarps = (gridDim.x * blockDim.x) >> 5;

    float2 bia = *reinterpret_cast<const float2*>(b + c0);
    float sx = 0.f, sy = 0.f, qx = 0.f, qy = 0.f;

    for (int node = warp; node < Nn; node += nwarps) {
        int r0 = g_rowptr[node], r1 = g_rowptr[node + 1];
        float ax0 = 0.f, ay0 = 0.f, ax1 = 0.f, ay1 = 0.f;
        int p = r0;
        for (; p + 4 <= r1; p += 4) {
            int s0 = g_cols[p], s1 = g_cols[p + 1], s2 = g_cols[p + 2], s3 = g_cols[p + 3];
            float2 v0 = *reinterpret_cast<const float2*>(hws + (size_t)s0 * 64 + c0);
            float2 v1 = *reinterpret_cast<const float2*>(hws + (size_t)s1 * 64 + c0);
            float2 v2 = *reinterpret_cast<const float2*>(hws + (size_t)s2 * 64 + c0);
            float2 v3 = *reinterpret_cast<const float2*>(hws + (size_t)s3 * 64 + c0);
            ax0 += v0.x + v2.x; ay0 += v0.y + v2.y;
            ax1 += v1.x + v3.x; ay1 += v1.y + v3.y;
        }
        for (; p < r1; p++) {
            int s = g_cols[p];
            float2 v = *reinterpret_cast<const float2*>(hws + (size_t)s * 64 + c0);
            ax0 += v.x; ay0 += v.y;
        }
        float2 self = *reinterpret_cast<const float2*>(hws + (size_t)node * 64 + c0);
        float dn = g_dis[node];
        float vx = dn * (ax0 + ax1 + self.x) + bia.x;
        float vy = dn * (ay0 + ay1 + self.y) + bia.y;
        *reinterpret_cast<float2*>(pre + (size_t)node * 64 + c0) = make_float2(vx, vy);
        sx += vx; sy += vy;
        qx += vx * vx; qy += vy * vy;
    }
    atomicAdd(&stats[c0], sx);
    atomicAdd(&stats[c0 + 1], sy);
    atomicAdd(&stats[64 + c0], qx);
    atomicAdd(&stats[64 + c0 + 1], qy);
}

// ---------------- gather (H=32/16): scalar lanes, one warp per node ----------------
template <int H>
__global__ void __launch_bounds__(256) k_gather(const float* __restrict__ hws,
                                                const float* __restrict__ b,
                                                float* __restrict__ pre,
                                                float* __restrict__ stats) {
    const int lane = threadIdx.x & 31;
    const int warp = (blockIdx.x * blockDim.x + threadIdx.x) >> 5;
    const int nwarps = (gridDim.x * blockDim.x) >> 5;
    const bool act = (H >= 32) || (lane < H);
    const int c = lane;

    float s_sum = 0.f, s_sq = 0.f;

    for (int node = warp; node < Nn; node += nwarps) {
        int r0 = g_rowptr[node], r1 = g_rowptr[node + 1];
        float acc = act ? hws[node * H + c] : 0.f;
        int p = r0;
        for (; p + 4 <= r1; p += 4) {
            int s0 = g_cols[p], s1 = g_cols[p + 1], s2 = g_cols[p + 2], s3 = g_cols[p + 3];
            if (act) {
                float v0 = hws[s0 * H + c];
                float v1 = hws[s1 * H + c];
                float v2 = hws[s2 * H + c];
                float v3 = hws[s3 * H + c];
                acc += (v0 + v1) + (v2 + v3);
            }
        }
        for (; p < r1; p++) {
            int s = g_cols[p];
            if (act) acc += hws[s * H + c];
        }
        if (act) {
            float dn = g_dis[node];
            float v = dn * acc + b[c];
            pre[node * H + c] = v;
            s_sum += v;
            s_sq += v * v;
        }
    }
    if (act) {
        atomicAdd(&stats[c], s_sum);
        atomicAdd(&stats[H + c], s_sq);
    }
}

// ---------------- pooling: per-graph sum/max/count over normalized x3 [N,16] ----------------
__device__ __forceinline__ int lower_bound_batch(const int* __restrict__ batch, int g) {
    int lo = 0, hi = Nn;
    while (lo < hi) {
        int m = (lo + hi) >> 1;
        if (batch[m] < g) lo = m + 1; else hi = m;
    }
    return lo;
}

__global__ void k_pool(const float* __restrict__ x3, const int* __restrict__ batch,
                       const float* __restrict__ stats,
                       const float* __restrict__ gamma, const float* __restrict__ beta) {
    __shared__ int ss, se;
    __shared__ float ssum[256], smax[256];
    int g = blockIdx.x, t = threadIdx.x;
    if (t == 0) { ss = lower_bound_batch(batch, g); se = lower_bound_batch(batch, g + 1); }
    __syncthreads();
    int s = ss, e = se;
    int c = t & 15;
    float m = stats[c] * (1.0f / Nn);
    float var = stats[16 + c] * (1.0f / Nn) - m * m;
    float rstd = rsqrtf(var + 1e-5f);
    float sc = rstd * gamma[c];
    float sh = beta[c] - m * sc;

    float sum = 0.f, mx = -3.402823466e+38f;
    for (int r = s + (t >> 4); r < e; r += 16) {
        float v = x3[r * 16 + c] * sc + sh;
        v = v > 0.f ? v : 0.1f * v;
        sum += v;
        mx = fmaxf(mx, v);
    }
    ssum[t] = sum; smax[t] = mx;
    __syncthreads();
    for (int off = 128; off >= 16; off >>= 1) {
        if (t < off) { ssum[t] += ssum[t + off]; smax[t] = fmaxf(smax[t], smax[t + off]); }
        __syncthreads();
    }
    if (t < 16) { g_pool[g * 33 + t] = ssum[t]; g_pool[g * 33 + 16 + t] = smax[t]; }
    if (t == 0) g_pool[g * 33 + 32] = (float)(e - s);
}

// ---------------- head: attention pooling + MLP + sigmoid ----------------
__global__ void k_head(const float* __restrict__ attn_w, const float* __restrict__ attn_b,
                       const float* __restrict__ fc1_w, const float* __restrict__ fc1_b,
                       const float* __restrict__ fc2_w, const float* __restrict__ fc2_b,
                       const float* __restrict__ out_w, const float* __restrict__ out_b,
                       float* __restrict__ out) {
    int g = threadIdx.x;
    if (g >= Gg) return;
    float sm[16], mx[16], mean[16];
    float cnt = g_pool[g * 33 + 32];
    float inv = 1.0f / fmaxf(cnt, 1.0f);
#pragma unroll
    for (int k = 0; k < 16; k++) {
        sm[k] = g_pool[g * 33 + k];
        mx[k] = g_pool[g * 33 + 16 + k];
        mean[k] = sm[k] * inv;
    }
    float z[3];
#pragma unroll
    for (int j = 0; j < 3; j++) z[j] = attn_b[j];
#pragma unroll
    for (int k = 0; k < 16; k++) {
#pragma unroll
        for (int j = 0; j < 3; j++) {
            z[j] += mean[k] * attn_w[k * 3 + j]
                  + mx[k]   * attn_w[(16 + k) * 3 + j]
                  + sm[k]   * attn_w[(32 + k) * 3 + j];
        }
    }
    float zm = fmaxf(z[0], fmaxf(z[1], z[2]));
    float e0 = expf(z[0] - zm), e1 = expf(z[1] - zm), e2 = expf(z[2] - zm);
    float is = 1.f / (e0 + e1 + e2);
    float a0 = e0 * is, a1 = e1 * is, a2 = e2 * is;
    float xg[16];
#pragma unroll
    for (int k = 0; k < 16; k++) xg[k] = a0 * mean[k] + a1 * mx[k] + a2 * sm[k];
    float y1[16];
#pragma unroll
    for (int j = 0; j < 16; j++) {
        float acc = fc1_b[j];
#pragma unroll
        for (int k = 0; k < 16; k++) acc += xg[k] * fc1_w[k * 16 + j];
        y1[j] = acc > 0.f ? acc : 0.1f * acc;
    }
    float y2[8];
#pragma unroll
    for (int j = 0; j < 8; j++) {
        float acc = fc2_b[j];
#pragma unroll
        for (int k = 0; k < 16; k++) acc += y1[k] * fc2_w[k * 8 + j];
        y2[j] = acc > 0.f ? acc : 0.1f * acc;
    }
    float o = out_b[0];
#pragma unroll
    for (int k = 0; k < 8; k++) o += y2[k] * out_w[k];
    out[g] = 1.f / (1.f + expf(-o));
}

// ---------------- host launch ----------------
extern "C" void kernel_launch(void* const* d_in, const int* in_sizes, int n_in,
                              void* d_out, int out_size) {
    const float* x      = (const float*)d_in[0];
    const float* W1     = (const float*)d_in[1];
    const float* b1     = (const float*)d_in[2];
    const float* W2     = (const float*)d_in[3];
    const float* b2     = (const float*)d_in[4];
    const float* W3     = (const float*)d_in[5];
    const float* b3     = (const float*)d_in[6];
    const float* g1     = (const float*)d_in[7];
    const float* be1    = (const float*)d_in[8];
    const float* g2     = (const float*)d_in[9];
    const float* be2    = (const float*)d_in[10];
    const float* g3     = (const float*)d_in[11];
    const float* be3    = (const float*)d_in[12];
    const float* attn_w = (const float*)d_in[13];
    const float* attn_b = (const float*)d_in[14];
    const float* fc1_w  = (const float*)d_in[15];
    const float* fc1_b  = (const float*)d_in[16];
    const float* fc2_w  = (const float*)d_in[17];
    const float* fc2_b  = (const float*)d_in[18];
    const float* out_w  = (const float*)d_in[19];
    const float* out_b  = (const float*)d_in[20];
    const int*   ei     = (const int*)d_in[21];
    const int*   batch  = (const int*)d_in[22];

    const int* src = ei;
    const int* dst = ei + Ee;
    float* out = (float*)d_out;

    void *pA = nullptr, *pB = nullptr, *pS = nullptr;
    cudaGetSymbolAddress(&pA, g_bufA);
    cudaGetSymbolAddress(&pB, g_bufB);
    cudaGetSymbolAddress(&pS, g_stats);
    float* bufA = (float*)pA;
    float* bufB = (float*)pB;
    float* st0 = (float*)pS;          // layer1 stats (sum[64], sq[64])
    float* st1 = st0 + 128;           // layer2 stats (sum[32], sq[32])
    float* st2 = st0 + 256;           // layer3 stats (sum[16], sq[16])

    static cudaStream_t sB = nullptr;
    static cudaEvent_t evFork = nullptr, evJoin = nullptr;
    if (sB == nullptr) {
        cudaStreamCreateWithFlags(&sB, cudaStreamNonBlocking);
        cudaEventCreateWithFlags(&evFork, cudaEventDisableTiming);
        cudaEventCreateWithFlags(&evJoin, cudaEventDisableTiming);
    }

    const int gemm_grid = (Nn + 127) / 128;   // 782
    const int gather_grid = 1184;             // 148 SMs * 8 blocks

    // ---- prefix: degree (+dis fused into scan1) ----
    k_zero<<<(Nn + 255) / 256, 256>>>();                       // 0
    k_hist<<<(Ee + 255) / 256, 256>>>(dst);                    // 1
    k_scan1<<<SCAN_NB, 512>>>();                               // 2 (block sums + dis)
    cudaEventRecord(evFork, 0);

    // ---- branch B: GEMM1 (needs only dis) ----
    cudaStreamWaitEvent(sB, evFork, 0);
    k_gemm<128, 64, false><<<gemm_grid, 256, 0, sB>>>(x, W1, nullptr, nullptr, nullptr, bufA); // 3
    cudaEventRecord(evJoin, sB);

    // ---- branch A (main): rowptr/cursor + fill ----
    k_scan3<<<SCAN_NB, 512>>>();                               // 4 (scan2 fused)
    k_fill<<<(Ee + 255) / 256, 256>>>(src, dst);               // 5

    // ---- join: gather needs CSR + GEMM1 output ----
    cudaStreamWaitEvent(0, evJoin, 0);
    k_gather64<<<gather_grid, 256>>>(bufA, b1, bufB, st0);     // 6

    // Layer 2: 64 -> 32 (BN1 + lrelu fused into GEMM load)
    k_gemm<64, 32, true><<<gemm_grid, 256>>>(bufB, W2, st0, g1, be1, bufA);   // 7
    k_gather<32><<<gather_grid, 256>>>(bufA, b2, bufB, st1);   // 8

    // Layer 3: 32 -> 16 (BN2 + lrelu fused into GEMM load)
    k_gemm<32, 16, true><<<gemm_grid, 256>>>(bufB, W3, st1, g2, be2, bufA);   // 9
    k_gather<16><<<gather_grid, 256>>>(bufA, b3, bufB, st2);   // 10

    // Pool (BN3 + lrelu fused) + head
    k_pool<<<Gg, 256>>>(bufB, batch, st2, g3, be3);            // 11
    k_head<<<1, 64>>>(attn_w, attn_b, fc1_w, fc1_b, fc2_w, fc2_b, out_w, out_b, out); // 12
}

// round 7
// speedup vs baseline: 1.1204x; 1.1204x over previous
#include <cuda_runtime.h>
#include <cuda_bf16.h>
#include <math.h>

#define Nn 100000
#define Ee 1600000
#define Gg 64

// ---------------- packed f32x2 helpers ----------------
#define PACK2(out, a, b) \
    asm("mov.b64 %0, {%1, %2};" : "=l"(out) : "f"(a), "f"(b))
#define FMA2(acc, a, b) \
    asm("fma.rn.f32x2 %0, %1, %2, %0;" : "+l"(acc) : "l"(a), "l"(b))

// ---------------- device scratch (static, no runtime allocation) ----------------
__device__ int   g_cnt[Nn];
__device__ int   g_rowptr[Nn + 1];
__device__ int   g_cursor[Nn];
__device__ int   g_cols[Ee];
__device__ float g_dis[Nn];
__device__ float g_bufA[Nn * 64];
__device__ float g_bufB[Nn * 64];
__device__ float g_stats[3 * 128];      // per layer: [0..H) sum, [H..2H) sumsq
__device__ int   g_bsum[256];           // scan partials
__device__ float g_pool[Gg * 33];       // per graph: sum[16], max[16], count

// ---------------- small utility kernels ----------------
__global__ void k_zero() {
    int i = blockIdx.x * 256 + threadIdx.x;
    if (i < Nn) g_cnt[i] = 0;
    if (i < 3 * 128) g_stats[i] = 0.f;
}
__global__ void k_hist(const int* __restrict__ dst) {
    int e = blockIdx.x * 256 + threadIdx.x;
    if (e < Ee) atomicAdd(&g_cnt[dst[e]], 1);
}
__global__ void k_dis() {
    int i = blockIdx.x * 256 + threadIdx.x;
    if (i < Nn) g_dis[i] = rsqrtf((float)(g_cnt[i] + 1));
}

#define SCAN_NB 196   // 196 * 512 = 100352 >= Nn

__global__ void k_scan1() {
    __shared__ int sh[512];
    int t = threadIdx.x, idx = blockIdx.x * 512 + t;
    sh[t] = (idx < Nn) ? g_cnt[idx] : 0;
    __syncthreads();
    for (int off = 256; off > 0; off >>= 1) {
        if (t < off) sh[t] += sh[t + off];
        __syncthreads();
    }
    if (t == 0) g_bsum[blockIdx.x] = sh[0];
}
__global__ void k_scan2() {
    __shared__ int sh[256];
    int t = threadIdx.x;
    int v = (t < SCAN_NB) ? g_bsum[t] : 0;
    sh[t] = v;
    __syncthreads();
    for (int off = 1; off < 256; off <<= 1) {
        int add = (t >= off) ? sh[t - off] : 0;
        __syncthreads();
        sh[t] += add;
        __syncthreads();
    }
    if (t < SCAN_NB) g_bsum[t] = sh[t] - v;   // exclusive
    if (t == 0) g_rowptr[Nn] = Ee;
}
__global__ void k_scan3() {
    __shared__ int sh[512];
    int t = threadIdx.x, idx = blockIdx.x * 512 + t;
    int v = (idx < Nn) ? g_cnt[idx] : 0;
    sh[t] = v;
    __syncthreads();
    for (int off = 1; off < 512; off <<= 1) {
        int add = (t >= off) ? sh[t - off] : 0;
        __syncthreads();
        sh[t] += add;
        __syncthreads();
    }
    if (idx < Nn) {
        int ex = g_bsum[blockIdx.x] + sh[t] - v;
        g_rowptr[idx] = ex;
        g_cursor[idx] = ex;
    }
}
__global__ void k_fill(const int* __restrict__ src, const int* __restrict__ dst) {
    int e = blockIdx.x * 256 + threadIdx.x;
    if (e < Ee) {
        int d = dst[e];
        int p = atomicAdd(&g_cursor[d], 1);
        g_cols[p] = src[e];
    }
}

// ---------------- GEMM (transposed-x register tile, packed f32x2 FMA) ----------------
// out[i,c] = scale * sum_k f(h[i,k]) * W[k,c]
// scale = dis[i] when PRESCALE, else 1 (raw product; dis applied in the gather).
// f = identity (NORM=false) or BN-normalize + leaky relu (NORM=true).
// block = 128 threads, tile = 128 nodes. Thread owns 4 consecutive nodes
// ((tid&31)*4 ..+3) and C=H/4 channels (group tid>>5). x staged TRANSPOSED in smem.
template <int K, int H, bool NORM, bool PRESCALE>
__global__ void __launch_bounds__(128, 4) k_gemm(const float* __restrict__ h,
                                                 const float* __restrict__ W,
                                                 const float* __restrict__ stats,
                                                 const float* __restrict__ gamma,
                                                 const float* __restrict__ beta,
                                                 float* __restrict__ out) {
    constexpr int C = H / 4;              // channels per thread
    __shared__ float Wsm[16 * H];         // current k-chunk of W
    __shared__ float xt[16][128];         // transposed x chunk
    __shared__ float nsc[K], nsh[K];
    const int tid = threadIdx.x;
    const int base = blockIdx.x * 128;
    const int n0 = (tid & 31) * 4;        // first of 4 owned nodes (local)
    const int cg = tid >> 5;              // channel group 0..3
    const int cbase = cg * C;

    if (NORM) {
        for (int c = tid; c < K; c += 128) {
            float m = stats[c] * (1.0f / Nn);
            float var = stats[K + c] * (1.0f / Nn) - m * m;
            float rstd = rsqrtf(var + 1e-5f);
            float sc = rstd * gamma[c];
            nsc[c] = sc;
            nsh[c] = beta[c] - m * sc;
        }
        __syncthreads();
    }

    unsigned long long acc2[4][C / 2];
#pragma unroll
    for (int t = 0; t < 4; t++)
#pragma unroll
        for (int j = 0; j < C / 2; j++) acc2[t][j] = 0ull;

    const int myrow = base + tid;         // staging row for this thread

    for (int kc = 0; kc < K; kc += 16) {
        // stage W chunk [16][H]
        {
            const float4* Wg = reinterpret_cast<const float4*>(W + kc * H);
            float4* Ws = reinterpret_cast<float4*>(Wsm);
#pragma unroll
            for (int i = tid; i < 16 * H / 4; i += 128) Ws[i] = Wg[i];
        }
        // stage x chunk transposed: xt[kk][tid] = f(h[base+tid][kc+kk])
#pragma unroll
        for (int q = 0; q < 4; q++) {
            float4 v = make_float4(0.f, 0.f, 0.f, 0.f);
            if (myrow < Nn)
                v = *reinterpret_cast<const float4*>(h + (size_t)myrow * K + kc + q * 4);
            if (NORM) {
                int cb = kc + q * 4;
                v.x = v.x * nsc[cb + 0] + nsh[cb + 0]; v.x = v.x > 0.f ? v.x : 0.1f * v.x;
                v.y = v.y * nsc[cb + 1] + nsh[cb + 1]; v.y = v.y > 0.f ? v.y : 0.1f * v.y;
                v.z = v.z * nsc[cb + 2] + nsh[cb + 2]; v.z = v.z > 0.f ? v.z : 0.1f * v.z;
                v.w = v.w * nsc[cb + 3] + nsh[cb + 3]; v.w = v.w > 0.f ? v.w : 0.1f * v.w;
            }
            xt[q * 4 + 0][tid] = v.x;
            xt[q * 4 + 1][tid] = v.y;
            xt[q * 4 + 2][tid] = v.z;
            xt[q * 4 + 3][tid] = v.w;
        }
        __syncthreads();
#pragma unroll
        for (int kk = 0; kk < 16; kk++) {
            float4 xv = *reinterpret_cast<const float4*>(&xt[kk][n0]);
            unsigned long long x0, x1, x2, x3;
            PACK2(x0, xv.x, xv.x);
            PACK2(x1, xv.y, xv.y);
            PACK2(x2, xv.z, xv.z);
            PACK2(x3, xv.w, xv.w);
            const ulonglong2* w2 =
                reinterpret_cast<const ulonglong2*>(&Wsm[kk * H + cbase]);
#pragma unroll
            for (int j = 0; j < C / 4; j++) {
                ulonglong2 w = w2[j];
                FMA2(acc2[0][2 * j + 0], x0, w.x);
                FMA2(acc2[0][2 * j + 1], x0, w.y);
                FMA2(acc2[1][2 * j + 0], x1, w.x);
                FMA2(acc2[1][2 * j + 1], x1, w.y);
                FMA2(acc2[2][2 * j + 0], x2, w.x);
                FMA2(acc2[2][2 * j + 1], x2, w.y);
                FMA2(acc2[3][2 * j + 0], x3, w.x);
                FMA2(acc2[3][2 * j + 1], x3, w.y);
            }
        }
        __syncthreads();
    }

    // epilogue: (optionally) scale by dis[node], store C channels x 4 nodes
#pragma unroll
    for (int t = 0; t < 4; t++) {
        int node = base + n0 + t;
        if (node < Nn) {
            float dn = PRESCALE ? g_dis[node] : 1.0f;
            const float* a = reinterpret_cast<const float*>(acc2[t]);
            float* o = out + (size_t)node * H + cbase;
#pragma unroll
            for (int j = 0; j < C / 4; j++) {
                float4 r;
                r.x = a[4 * j + 0] * dn;
                r.y = a[4 * j + 1] * dn;
                r.z = a[4 * j + 2] * dn;
                r.w = a[4 * j + 3] * dn;
                *reinterpret_cast<float4*>(o + 4 * j) = r;
            }
        }
    }
}

// ---------------- layer-1 gather (H=64), dis applied per edge ----------------
// pre[i] = dis[i]*( sum_e dis[src]*hw[src] + dis[i]*hw[i] ) + b
// one warp per node; lane owns channels {lane, lane+32}; fused BN stats.
__global__ void __launch_bounds__(256) k_gather1(const float* __restrict__ hw,
                                                 const float* __restrict__ b,
                                                 float* __restrict__ pre,
                                                 float* __restrict__ stats) {
    const int lane = threadIdx.x & 31;
    const int warp = (blockIdx.x * blockDim.x + threadIdx.x) >> 5;
    const int nwarps = (gridDim.x * blockDim.x) >> 5;
    const int c0 = lane, c1 = lane + 32;

    float s0 = 0.f, s1 = 0.f, q0 = 0.f, q1 = 0.f;

    for (int node = warp; node < Nn; node += nwarps) {
        int r0 = g_rowptr[node], r1 = g_rowptr[node + 1];
        float a0 = 0.f, a1 = 0.f;
        int p = r0;
        for (; p + 4 <= r1; p += 4) {
            int sA = g_cols[p], sB = g_cols[p + 1], sC = g_cols[p + 2], sD = g_cols[p + 3];
            float dA = g_dis[sA], dB = g_dis[sB], dC = g_dis[sC], dD = g_dis[sD];
            a0 += dA * hw[(size_t)sA * 64 + c0] + dB * hw[(size_t)sB * 64 + c0]
                + dC * hw[(size_t)sC * 64 + c0] + dD * hw[(size_t)sD * 64 + c0];
            a1 += dA * hw[(size_t)sA * 64 + c1] + dB * hw[(size_t)sB * 64 + c1]
                + dC * hw[(size_t)sC * 64 + c1] + dD * hw[(size_t)sD * 64 + c1];
        }
        for (; p < r1; p++) {
            int s = g_cols[p];
            float d = g_dis[s];
            a0 += d * hw[(size_t)s * 64 + c0];
            a1 += d * hw[(size_t)s * 64 + c1];
        }
        float dn = g_dis[node];
        float v0 = dn * (a0 + dn * hw[(size_t)node * 64 + c0]) + b[c0];
        float v1 = dn * (a1 + dn * hw[(size_t)node * 64 + c1]) + b[c1];
        pre[(size_t)node * 64 + c0] = v0;
        pre[(size_t)node * 64 + c1] = v1;
        s0 += v0; s1 += v1;
        q0 += v0 * v0; q1 += v1 * v1;
    }
    atomicAdd(&stats[c0], s0);
    atomicAdd(&stats[c1], s1);
    atomicAdd(&stats[64 + c0], q0);
    atomicAdd(&stats[64 + c1], q1);
}

// ---------------- gather (H=32/16, input pre-scaled by dis) ----------------
template <int H>
__global__ void __launch_bounds__(256) k_gather(const float* __restrict__ hws,
                                                const float* __restrict__ b,
                                                float* __restrict__ pre,
                                                float* __restrict__ stats) {
    const int lane = threadIdx.x & 31;
    const int warp = (blockIdx.x * blockDim.x + threadIdx.x) >> 5;
    const int nwarps = (gridDim.x * blockDim.x) >> 5;
    const bool act = (H >= 32) || (lane < H);
    const int c = lane;

    float s_sum = 0.f, s_sq = 0.f;

    for (int node = warp; node < Nn; node += nwarps) {
        int r0 = g_rowptr[node], r1 = g_rowptr[node + 1];
        float acc = act ? hws[node * H + c] : 0.f;
        int p = r0;
        for (; p + 4 <= r1; p += 4) {
            int s0 = g_cols[p], s1 = g_cols[p + 1], s2 = g_cols[p + 2], s3 = g_cols[p + 3];
            if (act) {
                float v0 = hws[s0 * H + c];
                float v1 = hws[s1 * H + c];
                float v2 = hws[s2 * H + c];
                float v3 = hws[s3 * H + c];
                acc += (v0 + v1) + (v2 + v3);
            }
        }
        for (; p < r1; p++) {
            int s = g_cols[p];
            if (act) acc += hws[s * H + c];
        }
        if (act) {
            float dn = g_dis[node];
            float v = dn * acc + b[c];
            pre[node * H + c] = v;
            s_sum += v;
            s_sq += v * v;
        }
    }
    if (act) {
        atomicAdd(&stats[c], s_sum);
        atomicAdd(&stats[H + c], s_sq);
    }
}

// ---------------- pooling: per-graph sum/max/count over normalized x3 [N,16] ----------------
__device__ __forceinline__ int lower_bound_batch(const int* __restrict__ batch, int g) {
    int lo = 0, hi = Nn;
    while (lo < hi) {
        int m = (lo + hi) >> 1;
        if (batch[m] < g) lo = m + 1; else hi = m;
    }
    return lo;
}

__global__ void k_pool(const float* __restrict__ x3, const int* __restrict__ batch,
                       const float* __restrict__ stats,
                       const float* __restrict__ gamma, const float* __restrict__ beta) {
    __shared__ int ss, se;
    __shared__ float ssum[256], smax[256];
    int g = blockIdx.x, t = threadIdx.x;
    if (t == 0) { ss = lower_bound_batch(batch, g); se = lower_bound_batch(batch, g + 1); }
    __syncthreads();
    int s = ss, e = se;
    int c = t & 15;
    float m = stats[c] * (1.0f / Nn);
    float var = stats[16 + c] * (1.0f / Nn) - m * m;
    float rstd = rsqrtf(var + 1e-5f);
    float sc = rstd * gamma[c];
    float sh = beta[c] - m * sc;

    float sum = 0.f, mx = -3.402823466e+38f;
    for (int r = s + (t >> 4); r < e; r += 16) {
        float v = x3[r * 16 + c] * sc + sh;
        v = v > 0.f ? v : 0.1f * v;
        sum += v;
        mx = fmaxf(mx, v);
    }
    ssum[t] = sum; smax[t] = mx;
    __syncthreads();
    for (int off = 128; off >= 16; off >>= 1) {
        if (t < off) { ssum[t] += ssum[t + off]; smax[t] = fmaxf(smax[t], smax[t + off]); }
        __syncthreads();
    }
    if (t < 16) { g_pool[g * 33 + t] = ssum[t]; g_pool[g * 33 + 16 + t] = smax[t]; }
    if (t == 0) g_pool[g * 33 + 32] = (float)(e - s);
}

// ---------------- head: attention pooling + MLP + sigmoid ----------------
__global__ void k_head(const float* __restrict__ attn_w, const float* __restrict__ attn_b,
                       const float* __restrict__ fc1_w, const float* __restrict__ fc1_b,
                       const float* __restrict__ fc2_w, const float* __restrict__ fc2_b,
                       const float* __restrict__ out_w, const float* __restrict__ out_b,
                       float* __restrict__ out) {
    int g = threadIdx.x;
    if (g >= Gg) return;
    float sm[16], mx[16], mean[16];
    float cnt = g_pool[g * 33 + 32];
    float inv = 1.0f / fmaxf(cnt, 1.0f);
#pragma unroll
    for (int k = 0; k < 16; k++) {
        sm[k] = g_pool[g * 33 + k];
        mx[k] = g_pool[g * 33 + 16 + k];
        mean[k] = sm[k] * inv;
    }
    float z[3];
#pragma unroll
    for (int j = 0; j < 3; j++) z[j] = attn_b[j];
#pragma unroll
    for (int k = 0; k < 16; k++) {
#pragma unroll
        for (int j = 0; j < 3; j++) {
            z[j] += mean[k] * attn_w[k * 3 + j]
                  + mx[k]   * attn_w[(16 + k) * 3 + j]
                  + sm[k]   * attn_w[(32 + k) * 3 + j];
        }
    }
    float zm = fmaxf(z[0], fmaxf(z[1], z[2]));
    float e0 = expf(z[0] - zm), e1 = expf(z[1] - zm), e2 = expf(z[2] - zm);
    float is = 1.f / (e0 + e1 + e2);
    float a0 = e0 * is, a1 = e1 * is, a2 = e2 * is;
    float xg[16];
#pragma unroll
    for (int k = 0; k < 16; k++) xg[k] = a0 * mean[k] + a1 * mx[k] + a2 * sm[k];
    float y1[16];
#pragma unroll
    for (int j = 0; j < 16; j++) {
        float acc = fc1_b[j];
#pragma unroll
        for (int k = 0; k < 16; k++) acc += xg[k] * fc1_w[k * 16 + j];
        y1[j] = acc > 0.f ? acc : 0.1f * acc;
    }
    float y2[8];
#pragma unroll
    for (int j = 0; j < 8; j++) {
        float acc = fc2_b[j];
#pragma unroll
        for (int k = 0; k < 16; k++) acc += y1[k] * fc2_w[k * 8 + j];
        y2[j] = acc > 0.f ? acc : 0.1f * acc;
    }
    float o = out_b[0];
#pragma unroll
    for (int k = 0; k < 8; k++) o += y2[k] * out_w[k];
    out[g] = 1.f / (1.f + expf(-o));
}

// ---------------- host launch ----------------
extern "C" void kernel_launch(void* const* d_in, const int* in_sizes, int n_in,
                              void* d_out, int out_size) {
    const float* x      = (const float*)d_in[0];
    const float* W1     = (const float*)d_in[1];
    const float* b1     = (const float*)d_in[2];
    const float* W2     = (const float*)d_in[3];
    const float* b2     = (const float*)d_in[4];
    const float* W3     = (const float*)d_in[5];
    const float* b3     = (const float*)d_in[6];
    const float* g1     = (const float*)d_in[7];
    const float* be1    = (const float*)d_in[8];
    const float* g2     = (const float*)d_in[9];
    const float* be2    = (const float*)d_in[10];
    const float* g3     = (const float*)d_in[11];
    const float* be3    = (const float*)d_in[12];
    const float* attn_w = (const float*)d_in[13];
    const float* attn_b = (const float*)d_in[14];
    const float* fc1_w  = (const float*)d_in[15];
    const float* fc1_b  = (const float*)d_in[16];
    const float* fc2_w  = (const float*)d_in[17];
    const float* fc2_b  = (const float*)d_in[18];
    const float* out_w  = (const float*)d_in[19];
    const float* out_b  = (const float*)d_in[20];
    const int*   ei     = (const int*)d_in[21];
    const int*   batch  = (const int*)d_in[22];

    const int* src = ei;
    const int* dst = ei + Ee;
    float* out = (float*)d_out;

    void *pA = nullptr, *pB = nullptr, *pS = nullptr;
    cudaGetSymbolAddress(&pA, g_bufA);
    cudaGetSymbolAddress(&pB, g_bufB);
    cudaGetSymbolAddress(&pS, g_stats);
    float* bufA = (float*)pA;
    float* bufB = (float*)pB;
    float* st0 = (float*)pS;          // layer1 stats (sum[64], sq[64])
    float* st1 = st0 + 128;           // layer2 stats (sum[32], sq[32])
    float* st2 = st0 + 256;           // layer3 stats (sum[16], sq[16])

    static cudaStream_t sB = nullptr;
    static cudaEvent_t evFork = nullptr, evJoin = nullptr;
    if (sB == nullptr) {
        cudaStreamCreateWithFlags(&sB, cudaStreamNonBlocking);
        cudaEventCreateWithFlags(&evFork, cudaEventDisableTiming);
        cudaEventCreateWithFlags(&evJoin, cudaEventDisableTiming);
    }

    const int gemm_grid = (Nn + 127) / 128;   // 782
    const int gather_grid = 1184;             // 148 SMs * 8 blocks

    // ---- fork at t=0: GEMM1 is dependency-free (raw x@W1, no dis) ----
    cudaEventRecord(evFork, 0);
    cudaStreamWaitEvent(sB, evFork, 0);
    k_gemm<128, 64, false, false><<<gemm_grid, 128, 0, sB>>>(x, W1, nullptr, nullptr, nullptr, bufA);
    cudaEventRecord(evJoin, sB);

    // ---- main stream: full CSR chain, overlapped with GEMM1 ----
    k_zero<<<(Nn + 255) / 256, 256>>>();
    k_hist<<<(Ee + 255) / 256, 256>>>(dst);
    k_dis<<<(Nn + 255) / 256, 256>>>();
    k_scan1<<<SCAN_NB, 512>>>();
    k_scan2<<<1, 256>>>();
    k_scan3<<<SCAN_NB, 512>>>();
    k_fill<<<(Ee + 255) / 256, 256>>>(src, dst);

    // ---- join: layer-1 gather needs CSR + raw GEMM1 output ----
    cudaStreamWaitEvent(0, evJoin, 0);
    k_gather1<<<gather_grid, 256>>>(bufA, b1, bufB, st0);

    // Layer 2: 64 -> 32 (BN1 + lrelu fused into GEMM load, dis pre-scaled)
    k_gemm<64, 32, true, true><<<gemm_grid, 128>>>(bufB, W2, st0, g1, be1, bufA);
    k_gather<32><<<gather_grid, 256>>>(bufA, b2, bufB, st1);

    // Layer 3: 32 -> 16 (BN2 + lrelu fused into GEMM load, dis pre-scaled)
    k_gemm<32, 16, true, true><<<gemm_grid, 128>>>(bufB, W3, st1, g2, be2, bufA);
    k_gather<16><<<gather_grid, 256>>>(bufA, b3, bufB, st2);

    // Pool (BN3 + lrelu fused) + head
    k_pool<<<Gg, 256>>>(bufB, batch, st2, g3, be3);
    k_head<<<1, 64>>>(attn_w, attn_b, fc1_w, fc1_b, fc2_w, fc2_b, out_w, out_b, out);
}